// round 5
// baseline (speedup 1.0000x reference)
#include <cuda_runtime.h>
#include <cstdint>
#include <math.h>

// Problem constants
#define B_ 4
#define M_ 2048
#define H_ 1024
#define I_ 4096

// ---------------- scratch (one __device__ symbol, carved into buffers) ------
#define OFF_Q     0L
#define OFF_KU    8388608L
#define OFF_VU    16777216L
#define OFF_KT    25165824L
#define OFF_VT    33554432L
#define OFF_SC    41943040L
#define OFF_CTX   58720256L
#define OFF_AO    67108864L
#define OFF_INTER 75497472L
#define OFF_TMP   109051904L
#define OFF_PD    117440512L
#define SCRATCH_TOTAL 117448704L

__device__ float g_scratch[SCRATCH_TOTAL];

// ---------------- helpers ---------------------------------------------------
__device__ __forceinline__ uint32_t f2tf32(float x) {
    uint32_t u;
    asm("cvt.rna.tf32.f32 %0, %1;" : "=r"(u) : "f"(x));
    return u;
}

// 2-term tf32 split: x ~= hi + lo, |x - hi - lo| <~ 2^-24 |x|
__device__ __forceinline__ void split_tf32(float x, uint32_t& hi, uint32_t& lo) {
    hi = f2tf32(x);
    lo = f2tf32(x - __uint_as_float(hi));
}

__device__ __forceinline__ void cp_async16(void* smem_dst, const void* gmem_src) {
    uint32_t s = (uint32_t)__cvta_generic_to_shared(smem_dst);
    asm volatile("cp.async.cg.shared.global [%0], [%1], 16;" :: "r"(s), "l"(gmem_src));
}
__device__ __forceinline__ void cp_async_commit() {
    asm volatile("cp.async.commit_group;");
}
template<int N>
__device__ __forceinline__ void cp_async_wait() {
    asm volatile("cp.async.wait_group %0;" :: "n"(N));
}

__device__ __forceinline__ void mma_tf32(float c[4], const uint32_t a[4], const uint32_t b[2]) {
    asm volatile(
        "mma.sync.aligned.m16n8k8.row.col.f32.tf32.tf32.f32 "
        "{%0,%1,%2,%3}, {%4,%5,%6,%7}, {%8,%9}, {%0,%1,%2,%3};"
        : "+f"(c[0]), "+f"(c[1]), "+f"(c[2]), "+f"(c[3])
        : "r"(a[0]), "r"(a[1]), "r"(a[2]), "r"(a[3]), "r"(b[0]), "r"(b[1]));
}

// ---------------- tensor-core tf32-split GEMM --------------------------------
// C[M,N] = epi( A[M,K] @ B )   fp32 in/out, 3xTF32 mma (hi*hi + lo*hi + hi*lo),
// fp32 accumulate -> effectively fp32 precision (~1e-6 per GEMM).
// TRANSB=false: B is [K,N] row-major.  TRANSB=true: B is [N,K] (C = A @ B^T).
// Block tile 128x128, BK=16, 256 threads (8 warps), warp tile 64x32,
// 3-stage cp.async pipeline, ONE __syncthreads per K-iteration:
//   the stage written during iter it was last read in iter it-1; every thread
//   passes iter it's top barrier only after finishing those reads.
#define EPI_NONE      0
#define EPI_BIAS      1
#define EPI_BIAS_GELU 2
#define EPI_SCALE     3
#define EPI_BIAS_RES  4

#define SA 20    // padded stride for [row][k] tiles: 20*4=80B = 5*16B, keeps
                 // cp.async 16B alignment; frag-read banks (20g+tq)%32 distinct.
#define SBN 136  // padded stride for [k][n] tile: read bank = (8*tq+g)%32,
                 // bijective over the warp's (tq,g) -> conflict-free.
#define NSTAGE 3

template<bool TRANSB, int EPI>
__global__ __launch_bounds__(256) void gemm_tc(
    const float* __restrict__ A, const float* __restrict__ Bm,
    const float* __restrict__ bias, const float* __restrict__ resid,
    float* __restrict__ C,
    int N, int K, long A_bs, long B_bs, long C_bs, float scale)
{
    A  += (long)blockIdx.z * A_bs;
    Bm += (long)blockIdx.z * B_bs;
    C  += (long)blockIdx.z * C_bs;

    // As: [128][SA] per stage.  Bs: trans -> [128][SA], non-trans -> [16][SBN].
    __shared__ __align__(16) float As[NSTAGE][128 * SA];
    __shared__ __align__(16) float Bs[NSTAGE][128 * SA > 16 * SBN ? 128 * SA : 16 * SBN];

    const int t    = threadIdx.x;
    const int w    = t >> 5;
    const int lane = t & 31;
    const int g    = lane >> 2;   // groupID 0..7
    const int tq   = lane & 3;    // thread-in-group 0..3
    const int wrow = (w >> 2) * 64;   // 0 / 64
    const int wcol = (w & 3) * 32;    // 0..96
    const int row0 = blockIdx.y * 128;
    const int col0 = blockIdx.x * 128;

    float acc[4][4][4];
    #pragma unroll
    for (int i = 0; i < 4; i++)
        #pragma unroll
        for (int j = 0; j < 4; j++)
            #pragma unroll
            for (int e = 0; e < 4; e++) acc[i][j][e] = 0.f;

    // global->smem copy assignments (8 floats = 2 x 16B per thread per tile)
    const int ar = t >> 1;          // 0..127
    const int ac = (t & 1) * 8;     // 0 / 8
    const int br = t >> 4;          // 0..15   (non-trans B)
    const int bc = (t & 15) * 8;    // 0..120

    const int nIter = K >> 4;

    // ---- tile loader ----
    auto load_tiles = [&](int k0, int buf) {
        const float* ag = A + (long)(row0 + ar) * K + (k0 + ac);
        cp_async16(&As[buf][ar * SA + ac],     ag);
        cp_async16(&As[buf][ar * SA + ac + 4], ag + 4);
        if (TRANSB) {
            const float* bg = Bm + (long)(col0 + ar) * K + (k0 + ac);
            cp_async16(&Bs[buf][ar * SA + ac],     bg);
            cp_async16(&Bs[buf][ar * SA + ac + 4], bg + 4);
        } else {
            const float* bg = Bm + (long)(k0 + br) * N + (col0 + bc);
            cp_async16(&Bs[buf][br * SBN + bc],     bg);
            cp_async16(&Bs[buf][br * SBN + bc + 4], bg + 4);
        }
    };

    // prologue: two tiles in flight
    load_tiles(0, 0);
    cp_async_commit();
    if (nIter > 1) { load_tiles(16, 1); cp_async_commit(); }

    int buf = 0;
    for (int it = 0; it < nIter; it++) {
        // ensure group for tile `it` has landed (<=1 newer group outstanding)
        if (it + 1 < nIter) cp_async_wait<1>(); else cp_async_wait<0>();
        __syncthreads();

        // prefetch tile it+2 into the free stage, overlapping compute
        if (it + 2 < nIter) {
            int nb = buf + 2; if (nb >= NSTAGE) nb -= NSTAGE;
            load_tiles((it + 2) << 4, nb);
            cp_async_commit();
        }

        #pragma unroll
        for (int ks = 0; ks < 2; ks++) {
            const int k8 = ks * 8;
            uint32_t ah[4][4], al[4][4], bh[4][2], bl[4][2];
            #pragma unroll
            for (int i = 0; i < 4; i++) {
                const int r = wrow + 16 * i;
                split_tf32(As[buf][(r + g)     * SA + k8 + tq],     ah[i][0], al[i][0]);
                split_tf32(As[buf][(r + g + 8) * SA + k8 + tq],     ah[i][1], al[i][1]);
                split_tf32(As[buf][(r + g)     * SA + k8 + tq + 4], ah[i][2], al[i][2]);
                split_tf32(As[buf][(r + g + 8) * SA + k8 + tq + 4], ah[i][3], al[i][3]);
            }
            #pragma unroll
            for (int j = 0; j < 4; j++) {
                const int cc = wcol + 8 * j + g;
                if (TRANSB) {
                    split_tf32(Bs[buf][cc * SA + k8 + tq],     bh[j][0], bl[j][0]);
                    split_tf32(Bs[buf][cc * SA + k8 + tq + 4], bh[j][1], bl[j][1]);
                } else {
                    split_tf32(Bs[buf][(k8 + tq)     * SBN + cc], bh[j][0], bl[j][0]);
                    split_tf32(Bs[buf][(k8 + tq + 4) * SBN + cc], bh[j][1], bl[j][1]);
                }
            }
            #pragma unroll
            for (int i = 0; i < 4; i++)
                #pragma unroll
                for (int j = 0; j < 4; j++) {
                    mma_tf32(acc[i][j], al[i], bh[j]);   // lo*hi
                    mma_tf32(acc[i][j], ah[i], bl[j]);   // hi*lo
                    mma_tf32(acc[i][j], ah[i], bh[j]);   // hi*hi
                }
        }
        // no trailing barrier: stage `buf` is only rewritten at iter it+1,
        // after every thread has passed that iteration's top barrier.
        buf = buf + 1 == NSTAGE ? 0 : buf + 1;
    }

    // ---- epilogue: each thread owns 2-wide strips ----
    #pragma unroll
    for (int i = 0; i < 4; i++) {
        #pragma unroll
        for (int j = 0; j < 4; j++) {
            const int cbase = col0 + wcol + 8 * j + 2 * tq;
            #pragma unroll
            for (int half = 0; half < 2; half++) {   // c0/c1 then c2/c3
                const long r = row0 + wrow + 16 * i + g + half * 8;
                float v0 = acc[i][j][2 * half + 0];
                float v1 = acc[i][j][2 * half + 1];
                if (EPI == EPI_BIAS || EPI == EPI_BIAS_GELU || EPI == EPI_BIAS_RES) {
                    float2 bb = *(const float2*)(bias + cbase);
                    v0 += bb.x; v1 += bb.y;
                }
                if (EPI == EPI_SCALE) { v0 *= scale; v1 *= scale; }
                if (EPI == EPI_BIAS_GELU) {
                    v0 = 0.5f * v0 * (1.0f + erff(v0 * 0.70710678118654752440f));
                    v1 = 0.5f * v1 * (1.0f + erff(v1 * 0.70710678118654752440f));
                }
                if (EPI == EPI_BIAS_RES) {
                    float2 rr = *(const float2*)(resid + r * N + cbase);
                    v0 += rr.x; v1 += rr.y;
                }
                *(float2*)(C + r * N + cbase) = make_float2(v0, v1);
            }
        }
    }
}

// ---------------- diagonal fix: scores[b,i,i] = scale * dot(q[b,i], ku[b,i])
__global__ void diag_fix_kernel(const float* __restrict__ q,
                                const float* __restrict__ ku,
                                float* __restrict__ scores, float scale)
{
    int warp = (blockIdx.x * blockDim.x + threadIdx.x) >> 5;
    int lane = threadIdx.x & 31;
    if (warp >= B_ * M_) return;
    const float* qr = q  + (long)warp * H_;
    const float* kr = ku + (long)warp * H_;
    float s = 0.f;
    #pragma unroll 4
    for (int h = lane; h < H_; h += 32) s += qr[h] * kr[h];
    #pragma unroll
    for (int o = 16; o; o >>= 1) s += __shfl_xor_sync(0xffffffffu, s, o);
    if (lane == 0) {
        long b = warp / M_, i = warp % M_;
        scores[(b * M_ + i) * M_ + i] = s * scale;
    }
}

// ---------------- row softmax over M_=2048, one block (256 thr) per row -----
__global__ __launch_bounds__(256) void softmax_kernel(float* __restrict__ scores,
                                                      float* __restrict__ pdiag)
{
    const long row = blockIdx.x;             // b*M + i
    float* sr = scores + row * M_;
    const int t = threadIdx.x;
    __shared__ float red[256];

    float v[8];
    float mx = -INFINITY;
    #pragma unroll
    for (int j = 0; j < 8; j++) { v[j] = sr[t + j * 256]; mx = fmaxf(mx, v[j]); }
    red[t] = mx; __syncthreads();
    for (int s = 128; s > 0; s >>= 1) { if (t < s) red[t] = fmaxf(red[t], red[t + s]); __syncthreads(); }
    mx = red[0]; __syncthreads();

    float sum = 0.f;
    #pragma unroll
    for (int j = 0; j < 8; j++) { v[j] = expf(v[j] - mx); sum += v[j]; }
    red[t] = sum; __syncthreads();
    for (int s = 128; s > 0; s >>= 1) { if (t < s) red[t] += red[t + s]; __syncthreads(); }
    const float inv = 1.0f / red[0];

    #pragma unroll
    for (int j = 0; j < 8; j++) sr[t + j * 256] = v[j] * inv;

    const int i = (int)(row % M_);
    if (t == (i & 255)) pdiag[row] = v[i >> 8] * inv;
}

// ---------------- ctx += pdiag[row] * (vu - vt), float4 ----------------------
__global__ void ctx_fix_kernel(float* __restrict__ ctx,
                               const float* __restrict__ vu,
                               const float* __restrict__ vt,
                               const float* __restrict__ pdiag)
{
    long idx4 = (long)blockIdx.x * blockDim.x + threadIdx.x;
    if (idx4 >= (long)B_ * M_ * H_ / 4) return;
    long row = idx4 / (H_ / 4);
    float pd = pdiag[row];
    float4 c = ((float4*)ctx)[idx4];
    float4 a = ((const float4*)vu)[idx4];
    float4 b = ((const float4*)vt)[idx4];
    c.x += pd * (a.x - b.x);
    c.y += pd * (a.y - b.y);
    c.z += pd * (a.z - b.z);
    c.w += pd * (a.w - b.w);
    ((float4*)ctx)[idx4] = c;
}

// ---------------- LayerNorm over H_=1024, one block (256 thr) per row -------
__global__ __launch_bounds__(256) void layernorm_kernel(const float* __restrict__ x,
                                                        const float* __restrict__ g,
                                                        const float* __restrict__ b,
                                                        float* __restrict__ out)
{
    const long row = blockIdx.x;
    const int t = threadIdx.x;
    __shared__ float red[256];

    float4 v = *(const float4*)(x + row * H_ + t * 4);
    red[t] = v.x + v.y + v.z + v.w;
    __syncthreads();
    for (int s = 128; s > 0; s >>= 1) { if (t < s) red[t] += red[t + s]; __syncthreads(); }
    const float mu = red[0] * (1.0f / H_);
    __syncthreads();

    float dx = v.x - mu, dy = v.y - mu, dz = v.z - mu, dw = v.w - mu;
    red[t] = dx * dx + dy * dy + dz * dz + dw * dw;
    __syncthreads();
    for (int s = 128; s > 0; s >>= 1) { if (t < s) red[t] += red[t + s]; __syncthreads(); }
    const float rstd = rsqrtf(red[0] * (1.0f / H_) + 1e-12f);

    float4 gv = *(const float4*)(g + t * 4);
    float4 bv = *(const float4*)(b + t * 4);
    float4 o;
    o.x = dx * rstd * gv.x + bv.x;
    o.y = dy * rstd * gv.y + bv.y;
    o.z = dz * rstd * gv.z + bv.z;
    o.w = dw * rstd * gv.w + bv.w;
    *(float4*)(out + row * H_ + t * 4) = o;
}

// ============================================================================
extern "C" void kernel_launch(void* const* d_in, const int* in_sizes, int n_in,
                              void* d_out, int out_size)
{
    const float* ht   = (const float*)d_in[0];
    const float* hu   = (const float*)d_in[1];
    // d_in[2] = attention_mask (int32): per-row constant added before a row
    // softmax over that same axis -> provably a no-op; dropped.
    const float* Wq   = (const float*)d_in[3];
    const float* bq   = (const float*)d_in[4];
    const float* Wk   = (const float*)d_in[5];
    const float* bk   = (const float*)d_in[6];
    const float* Wv   = (const float*)d_in[7];
    const float* bv   = (const float*)d_in[8];
    const float* Wo   = (const float*)d_in[9];
    const float* bo   = (const float*)d_in[10];
    const float* ln1g = (const float*)d_in[11];
    const float* ln1b = (const float*)d_in[12];
    const float* W1   = (const float*)d_in[13];
    const float* b1   = (const float*)d_in[14];
    const float* W2   = (const float*)d_in[15];
    const float* b2   = (const float*)d_in[16];
    const float* ln2g = (const float*)d_in[17];
    const float* ln2b = (const float*)d_in[18];
    float* out = (float*)d_out;

    float* scr = nullptr;
    cudaGetSymbolAddress((void**)&scr, g_scratch);
    float* q     = scr + OFF_Q;
    float* ku    = scr + OFF_KU;
    float* vu    = scr + OFF_VU;
    float* kt    = scr + OFF_KT;
    float* vt    = scr + OFF_VT;
    float* sc    = scr + OFF_SC;
    float* ctx   = scr + OFF_CTX;
    float* ao    = scr + OFF_AO;
    float* inter = scr + OFF_INTER;
    float* tmp   = scr + OFF_TMP;
    float* pd    = scr + OFF_PD;

    const int BMrows = B_ * M_;               // 8192
    const float scale = 0.03125f;             // 1/sqrt(1024)

    dim3 thr(256);

    // 1) projections: [8192,1024] x [1024,1024] (+bias)
    {
        dim3 grid(H_ / 128, BMrows / 128, 1);
        gemm_tc<false, EPI_BIAS><<<grid, thr>>>(hu, Wq, bq, nullptr, q,  H_, H_, 0, 0, 0, 0.f);
        gemm_tc<false, EPI_BIAS><<<grid, thr>>>(hu, Wk, bk, nullptr, ku, H_, H_, 0, 0, 0, 0.f);
        gemm_tc<false, EPI_BIAS><<<grid, thr>>>(hu, Wv, bv, nullptr, vu, H_, H_, 0, 0, 0, 0.f);
        gemm_tc<false, EPI_BIAS><<<grid, thr>>>(ht, Wk, bk, nullptr, kt, H_, H_, 0, 0, 0, 0.f);
        gemm_tc<false, EPI_BIAS><<<grid, thr>>>(ht, Wv, bv, nullptr, vt, H_, H_, 0, 0, 0, 0.f);
    }

    // 2) scores[b] = scale * q[b] @ kt[b]^T   (batched NT)
    {
        dim3 grid(M_ / 128, M_ / 128, B_);
        gemm_tc<true, EPI_SCALE><<<grid, thr>>>(q, kt, nullptr, nullptr, sc,
            M_, H_, (long)M_ * H_, (long)M_ * H_, (long)M_ * M_, scale);
    }

    // 3) overwrite diagonal with scale * dot(q, ku)   (fp32)
    diag_fix_kernel<<<(BMrows * 32 + 255) / 256, thr>>>(q, ku, sc, scale);

    // 4) row softmax (+ extract p_diag)
    softmax_kernel<<<BMrows, thr>>>(sc, pd);

    // 5) ctx[b] = probs[b] @ vt[b]   (batched NN)
    {
        dim3 grid(H_ / 128, M_ / 128, B_);
        gemm_tc<false, EPI_NONE><<<grid, thr>>>(sc, vt, nullptr, nullptr, ctx,
            H_, M_, (long)M_ * M_, (long)M_ * H_, (long)M_ * H_, 0.f);
    }

    // 6) ctx += p_diag * (vu - vt)
    ctx_fix_kernel<<<(int)((long)B_ * M_ * H_ / 4 / 256), thr>>>(ctx, vu, vt, pd);

    // 7) attn_out = LN1(ctx @ Wo + bo)
    {
        dim3 grid(H_ / 128, BMrows / 128, 1);
        gemm_tc<false, EPI_BIAS><<<grid, thr>>>(ctx, Wo, bo, nullptr, tmp, H_, H_, 0, 0, 0, 0.f);
    }
    layernorm_kernel<<<BMrows, thr>>>(tmp, ln1g, ln1b, ao);

    // 8) inter = gelu_exact(attn_out @ W1 + b1)
    {
        dim3 grid(I_ / 128, BMrows / 128, 1);
        gemm_tc<false, EPI_BIAS_GELU><<<grid, thr>>>(ao, W1, b1, nullptr, inter, I_, H_, 0, 0, 0, 0.f);
    }

    // 9) tmp = inter @ W2 + b2 + attn_out ; out = LN2(tmp)
    {
        dim3 grid(H_ / 128, BMrows / 128, 1);
        gemm_tc<false, EPI_BIAS_RES><<<grid, thr>>>(inter, W2, b2, ao, tmp, H_, I_, 0, 0, 0, 0.f);
    }
    layernorm_kernel<<<BMrows, thr>>>(tmp, ln2g, ln2b, out);
}

// round 14
// speedup vs baseline: 1.1802x; 1.1802x over previous
#include <cuda_runtime.h>
#include <cstdint>
#include <math.h>

// Problem constants
#define B_ 4
#define M_ 2048
#define H_ 1024
#define I_ 4096

// ---------------- scratch (one __device__ symbol, carved into buffers) ------
#define OFF_Q     0L
#define OFF_KU    8388608L
#define OFF_VU    16777216L
#define OFF_KT    25165824L
#define OFF_VT    33554432L
#define OFF_SC    41943040L
#define OFF_CTX   58720256L
#define OFF_AO    67108864L
#define OFF_INTER 75497472L
#define OFF_TMP   109051904L
#define OFF_PD    117440512L
#define SCRATCH_TOTAL 117448704L

__device__ float g_scratch[SCRATCH_TOTAL];

// ---------------- helpers ---------------------------------------------------
__device__ __forceinline__ uint32_t f2tf32(float x) {
    uint32_t u;
    asm("cvt.rna.tf32.f32 %0, %1;" : "=r"(u) : "f"(x));
    return u;
}

// 2-term tf32 split: x ~= hi + lo, |x - hi - lo| <~ 2^-24 |x|
__device__ __forceinline__ void split_tf32(float x, uint32_t& hi, uint32_t& lo) {
    hi = f2tf32(x);
    lo = f2tf32(x - __uint_as_float(hi));
}

__device__ __forceinline__ void cp_async16(void* smem_dst, const void* gmem_src) {
    uint32_t s = (uint32_t)__cvta_generic_to_shared(smem_dst);
    asm volatile("cp.async.cg.shared.global [%0], [%1], 16;" :: "r"(s), "l"(gmem_src));
}
__device__ __forceinline__ void cp_async_commit() {
    asm volatile("cp.async.commit_group;");
}
template<int N>
__device__ __forceinline__ void cp_async_wait() {
    asm volatile("cp.async.wait_group %0;" :: "n"(N));
}

__device__ __forceinline__ void mma_tf32(float c[4], const uint32_t a[4], const uint32_t b[2]) {
    asm volatile(
        "mma.sync.aligned.m16n8k8.row.col.f32.tf32.tf32.f32 "
        "{%0,%1,%2,%3}, {%4,%5,%6,%7}, {%8,%9}, {%0,%1,%2,%3};"
        : "+f"(c[0]), "+f"(c[1]), "+f"(c[2]), "+f"(c[3])
        : "r"(a[0]), "r"(a[1]), "r"(a[2]), "r"(a[3]), "r"(b[0]), "r"(b[1]));
}

// ---------------- tensor-core tf32-split GEMM body ---------------------------
// C[M,N] = epi( A[M,K] @ B )   fp32 in/out, 3xTF32 mma (hi*hi + lo*hi + hi*lo),
// fp32 accumulate -> effectively fp32 precision (~1e-6 per GEMM).
// TRANSB=false: B is [K,N] row-major.  TRANSB=true: B is [N,K] (C = A @ B^T).
// Block tile 128x128, BK=16, 256 threads (8 warps), warp tile 64x32,
// 3-stage cp.async pipeline, ONE __syncthreads per K-iteration.
// Caller kernels use __launch_bounds__(256, 2): cap regs at 128 -> 2 CTAs/SM
// (R5 ncu: occ=12.5%, issue=37% at 1 CTA/SM was the limiter). Inner loop keeps
// live registers ~115 (B frags split per k-slice, A frags one row-block at a
// time) so the cap does not cause mainloop spills.
#define EPI_NONE      0
#define EPI_BIAS      1
#define EPI_BIAS_GELU 2
#define EPI_SCALE     3
#define EPI_BIAS_RES  4
#define EPI_PDIAG     5   // C = acc + pd[r]*(vu[r,c]-vt[r,c])  (fused ctx_fix)

#define SA 20    // padded stride for [row][k] tiles: 20*4=80B = 5*16B, keeps
                 // cp.async 16B alignment; frag-read banks (20g+tq)%32 distinct.
#define SBN 136  // padded stride for [k][n] tile: read bank = (8*tq+g)%32,
                 // bijective over the warp's (tq,g) -> conflict-free.
#define NSTAGE 3

template<bool TRANSB, int EPI>
__device__ __forceinline__ void gemm_body(
    const float* __restrict__ A, const float* __restrict__ Bm,
    const float* __restrict__ bias, const float* __restrict__ resid,
    float* __restrict__ C, int N, int K, float scale,
    const float* __restrict__ pd, const float* __restrict__ vu,
    const float* __restrict__ vt)
{
    // As: [128][SA] per stage.  Bs: trans -> [128][SA], non-trans -> [16][SBN].
    __shared__ __align__(16) float As[NSTAGE][128 * SA];
    __shared__ __align__(16) float Bs[NSTAGE][128 * SA > 16 * SBN ? 128 * SA : 16 * SBN];

    const int t    = threadIdx.x;
    const int w    = t >> 5;
    const int lane = t & 31;
    const int g    = lane >> 2;   // groupID 0..7
    const int tq   = lane & 3;    // thread-in-group 0..3
    const int wrow = (w >> 2) * 64;   // 0 / 64
    const int wcol = (w & 3) * 32;    // 0..96
    const int row0 = blockIdx.y * 128;
    const int col0 = blockIdx.x * 128;

    float acc[4][4][4];
    #pragma unroll
    for (int i = 0; i < 4; i++)
        #pragma unroll
        for (int j = 0; j < 4; j++)
            #pragma unroll
            for (int e = 0; e < 4; e++) acc[i][j][e] = 0.f;

    // global->smem copy assignments (8 floats = 2 x 16B per thread per tile)
    const int ar = t >> 1;          // 0..127
    const int ac = (t & 1) * 8;     // 0 / 8
    const int br = t >> 4;          // 0..15   (non-trans B)
    const int bc = (t & 15) * 8;    // 0..120

    const int nIter = K >> 4;

    // ---- tile loader ----
    auto load_tiles = [&](int k0, int buf) {
        const float* ag = A + (long)(row0 + ar) * K + (k0 + ac);
        cp_async16(&As[buf][ar * SA + ac],     ag);
        cp_async16(&As[buf][ar * SA + ac + 4], ag + 4);
        if (TRANSB) {
            const float* bg = Bm + (long)(col0 + ar) * K + (k0 + ac);
            cp_async16(&Bs[buf][ar * SA + ac],     bg);
            cp_async16(&Bs[buf][ar * SA + ac + 4], bg + 4);
        } else {
            const float* bg = Bm + (long)(k0 + br) * N + (col0 + bc);
            cp_async16(&Bs[buf][br * SBN + bc],     bg);
            cp_async16(&Bs[buf][br * SBN + bc + 4], bg + 4);
        }
    };

    // prologue: two tiles in flight
    load_tiles(0, 0);
    cp_async_commit();
    if (nIter > 1) { load_tiles(16, 1); cp_async_commit(); }

    int buf = 0;
    for (int it = 0; it < nIter; it++) {
        // ensure group for tile `it` has landed (<=1 newer group outstanding)
        if (it + 1 < nIter) cp_async_wait<1>(); else cp_async_wait<0>();
        __syncthreads();

        // prefetch tile it+2 into the free stage, overlapping compute
        if (it + 2 < nIter) {
            int nb = buf + 2; if (nb >= NSTAGE) nb -= NSTAGE;
            load_tiles((it + 2) << 4, nb);
            cp_async_commit();
        }

        #pragma unroll
        for (int ks = 0; ks < 2; ks++) {
            const int k8 = ks * 8;
            // split B fragments once for this k-slice (16 live regs)
            uint32_t bh[4][2], bl[4][2];
            #pragma unroll
            for (int j = 0; j < 4; j++) {
                const int cc = wcol + 8 * j + g;
                if (TRANSB) {
                    split_tf32(Bs[buf][cc * SA + k8 + tq],     bh[j][0], bl[j][0]);
                    split_tf32(Bs[buf][cc * SA + k8 + tq + 4], bh[j][1], bl[j][1]);
                } else {
                    split_tf32(Bs[buf][(k8 + tq)     * SBN + cc], bh[j][0], bl[j][0]);
                    split_tf32(Bs[buf][(k8 + tq + 4) * SBN + cc], bh[j][1], bl[j][1]);
                }
            }
            // process A one 16-row block at a time (8 live regs instead of 32)
            #pragma unroll
            for (int i = 0; i < 4; i++) {
                const int r = wrow + 16 * i;
                uint32_t ah[4], al[4];
                split_tf32(As[buf][(r + g)     * SA + k8 + tq],     ah[0], al[0]);
                split_tf32(As[buf][(r + g + 8) * SA + k8 + tq],     ah[1], al[1]);
                split_tf32(As[buf][(r + g)     * SA + k8 + tq + 4], ah[2], al[2]);
                split_tf32(As[buf][(r + g + 8) * SA + k8 + tq + 4], ah[3], al[3]);
                #pragma unroll
                for (int j = 0; j < 4; j++) {
                    mma_tf32(acc[i][j], al, bh[j]);   // lo*hi
                    mma_tf32(acc[i][j], ah, bl[j]);   // hi*lo
                    mma_tf32(acc[i][j], ah, bh[j]);   // hi*hi
                }
            }
        }
        // no trailing barrier: stage `buf` is only rewritten at iter it+1,
        // after every thread has passed that iteration's top barrier.
        buf = buf + 1 == NSTAGE ? 0 : buf + 1;
    }

    // ---- epilogue: each thread owns 2-wide strips ----
    #pragma unroll
    for (int i = 0; i < 4; i++) {
        #pragma unroll
        for (int j = 0; j < 4; j++) {
            const int cbase = col0 + wcol + 8 * j + 2 * tq;
            #pragma unroll
            for (int half = 0; half < 2; half++) {   // c0/c1 then c2/c3
                const long r = row0 + wrow + 16 * i + g + half * 8;
                float v0 = acc[i][j][2 * half + 0];
                float v1 = acc[i][j][2 * half + 1];
                if (EPI == EPI_BIAS || EPI == EPI_BIAS_GELU || EPI == EPI_BIAS_RES) {
                    float2 bb = *(const float2*)(bias + cbase);
                    v0 += bb.x; v1 += bb.y;
                }
                if (EPI == EPI_SCALE) { v0 *= scale; v1 *= scale; }
                if (EPI == EPI_BIAS_GELU) {
                    v0 = 0.5f * v0 * (1.0f + erff(v0 * 0.70710678118654752440f));
                    v1 = 0.5f * v1 * (1.0f + erff(v1 * 0.70710678118654752440f));
                }
                if (EPI == EPI_BIAS_RES) {
                    float2 rr = *(const float2*)(resid + r * N + cbase);
                    v0 += rr.x; v1 += rr.y;
                }
                if (EPI == EPI_PDIAG) {
                    // fused ctx_fix: += pd[r]*(vu[r,c]-vt[r,c])
                    float pdv = pd[r];
                    float2 uu = *(const float2*)(vu + r * N + cbase);
                    float2 tt = *(const float2*)(vt + r * N + cbase);
                    v0 += pdv * (uu.x - tt.x);
                    v1 += pdv * (uu.y - tt.y);
                }
                *(float2*)(C + r * N + cbase) = make_float2(v0, v1);
            }
        }
    }
}

// general kernel (z-batched over batch dim for attention GEMMs)
template<bool TRANSB, int EPI>
__global__ __launch_bounds__(256, 2) void gemm_tc(
    const float* __restrict__ A, const float* __restrict__ Bm,
    const float* __restrict__ bias, const float* __restrict__ resid,
    float* __restrict__ C,
    int N, int K, long A_bs, long B_bs, long C_bs, float scale,
    const float* pd, const float* vu, const float* vt)
{
    A  += (long)blockIdx.z * A_bs;
    Bm += (long)blockIdx.z * B_bs;
    C  += (long)blockIdx.z * C_bs;
    if (EPI == EPI_PDIAG) {
        pd += (long)blockIdx.z * M_;       // one pdiag per row
        vu += (long)blockIdx.z * C_bs;     // same layout as C
        vt += (long)blockIdx.z * C_bs;
    }
    gemm_body<TRANSB, EPI>(A, Bm, bias, resid, C, N, K, scale, pd, vu, vt);
}

// fused projection kernel: blockIdx.z in [0,5) selects (A, W, bias, C).
// One launch of 2560 CTAs instead of 5x512 -> tail waste ~4% instead of ~14%/ea.
struct ProjBatch {
    const float* A[5];
    const float* W[5];
    const float* b[5];
    float*       C[5];
};

__global__ __launch_bounds__(256, 2) void gemm_proj_batch(ProjBatch pb, int N, int K)
{
    const int z = blockIdx.z;
    gemm_body<false, EPI_BIAS>(pb.A[z], pb.W[z], pb.b[z], nullptr, pb.C[z], N, K, 0.f,
                               nullptr, nullptr, nullptr);
}

// ---------------- fused diag + row softmax over M_=2048 ----------------------
// One block (256 thr) per row (b,i). First computes d = scale*dot(q[b,i],ku[b,i])
// in-block (replaces the old diag_fix kernel + its extra DRAM pass), then does
// the softmax with the diagonal element replaced by d at load time.
__global__ __launch_bounds__(256) void softmax_kernel(float* __restrict__ scores,
                                                      const float* __restrict__ q,
                                                      const float* __restrict__ ku,
                                                      float* __restrict__ pdiag,
                                                      float scale)
{
    const long row = blockIdx.x;             // b*M + i
    float* sr = scores + row * M_;
    const int t = threadIdx.x;
    __shared__ float red[256];

    // ---- diagonal dot-product: H_=1024 floats, one float4 per thread ----
    {
        float4 q4 = *(const float4*)(q  + row * H_ + t * 4);
        float4 k4 = *(const float4*)(ku + row * H_ + t * 4);
        red[t] = q4.x * k4.x + q4.y * k4.y + q4.z * k4.z + q4.w * k4.w;
    }
    __syncthreads();
    for (int s = 128; s > 0; s >>= 1) { if (t < s) red[t] += red[t + s]; __syncthreads(); }
    const float dval = red[0] * scale;
    __syncthreads();

    const int i = (int)(row % M_);           // diagonal column

    float v[8];
    float mx = -INFINITY;
    #pragma unroll
    for (int j = 0; j < 8; j++) {
        v[j] = sr[t + j * 256];
        if (t + j * 256 == i) v[j] = dval;   // replace diagonal at load
        mx = fmaxf(mx, v[j]);
    }
    red[t] = mx; __syncthreads();
    for (int s = 128; s > 0; s >>= 1) { if (t < s) red[t] = fmaxf(red[t], red[t + s]); __syncthreads(); }
    mx = red[0]; __syncthreads();

    float sum = 0.f;
    #pragma unroll
    for (int j = 0; j < 8; j++) { v[j] = expf(v[j] - mx); sum += v[j]; }
    red[t] = sum; __syncthreads();
    for (int s = 128; s > 0; s >>= 1) { if (t < s) red[t] += red[t + s]; __syncthreads(); }
    const float inv = 1.0f / red[0];

    #pragma unroll
    for (int j = 0; j < 8; j++) sr[t + j * 256] = v[j] * inv;

    if (t == (i & 255)) pdiag[row] = v[i >> 8] * inv;
}

// ---------------- LayerNorm over H_=1024, one block (256 thr) per row -------
__global__ __launch_bounds__(256) void layernorm_kernel(const float* __restrict__ x,
                                                        const float* __restrict__ g,
                                                        const float* __restrict__ b,
                                                        float* __restrict__ out)
{
    const long row = blockIdx.x;
    const int t = threadIdx.x;
    __shared__ float red[256];

    float4 v = *(const float4*)(x + row * H_ + t * 4);
    red[t] = v.x + v.y + v.z + v.w;
    __syncthreads();
    for (int s = 128; s > 0; s >>= 1) { if (t < s) red[t] += red[t + s]; __syncthreads(); }
    const float mu = red[0] * (1.0f / H_);
    __syncthreads();

    float dx = v.x - mu, dy = v.y - mu, dz = v.z - mu, dw = v.w - mu;
    red[t] = dx * dx + dy * dy + dz * dz + dw * dw;
    __syncthreads();
    for (int s = 128; s > 0; s >>= 1) { if (t < s) red[t] += red[t + s]; __syncthreads(); }
    const float rstd = rsqrtf(red[0] * (1.0f / H_) + 1e-12f);

    float4 gv = *(const float4*)(g + t * 4);
    float4 bv = *(const float4*)(b + t * 4);
    float4 o;
    o.x = dx * rstd * gv.x + bv.x;
    o.y = dy * rstd * gv.y + bv.y;
    o.z = dz * rstd * gv.z + bv.z;
    o.w = dw * rstd * gv.w + bv.w;
    *(float4*)(out + row * H_ + t * 4) = o;
}

// ============================================================================
extern "C" void kernel_launch(void* const* d_in, const int* in_sizes, int n_in,
                              void* d_out, int out_size)
{
    const float* ht   = (const float*)d_in[0];
    const float* hu   = (const float*)d_in[1];
    // d_in[2] = attention_mask (int32): per-row constant added before a row
    // softmax over that same axis -> provably a no-op; dropped.
    const float* Wq   = (const float*)d_in[3];
    const float* bq   = (const float*)d_in[4];
    const float* Wk   = (const float*)d_in[5];
    const float* bk   = (const float*)d_in[6];
    const float* Wv   = (const float*)d_in[7];
    const float* bv   = (const float*)d_in[8];
    const float* Wo   = (const float*)d_in[9];
    const float* bo   = (const float*)d_in[10];
    const float* ln1g = (const float*)d_in[11];
    const float* ln1b = (const float*)d_in[12];
    const float* W1   = (const float*)d_in[13];
    const float* b1   = (const float*)d_in[14];
    const float* W2   = (const float*)d_in[15];
    const float* b2   = (const float*)d_in[16];
    const float* ln2g = (const float*)d_in[17];
    const float* ln2b = (const float*)d_in[18];
    float* out = (float*)d_out;

    float* scr = nullptr;
    cudaGetSymbolAddress((void**)&scr, g_scratch);
    float* q     = scr + OFF_Q;
    float* ku    = scr + OFF_KU;
    float* vu    = scr + OFF_VU;
    float* kt    = scr + OFF_KT;
    float* vt    = scr + OFF_VT;
    float* sc    = scr + OFF_SC;
    float* ctx   = scr + OFF_CTX;
    float* ao    = scr + OFF_AO;
    float* inter = scr + OFF_INTER;
    float* tmp   = scr + OFF_TMP;
    float* pd    = scr + OFF_PD;

    const int BMrows = B_ * M_;               // 8192
    const float scale = 0.03125f;             // 1/sqrt(1024)

    dim3 thr(256);

    // 1) all 5 projections in ONE launch: [8192,1024] x [1024,1024] (+bias)
    {
        ProjBatch pb;
        pb.A[0] = hu; pb.W[0] = Wq; pb.b[0] = bq; pb.C[0] = q;
        pb.A[1] = hu; pb.W[1] = Wk; pb.b[1] = bk; pb.C[1] = ku;
        pb.A[2] = hu; pb.W[2] = Wv; pb.b[2] = bv; pb.C[2] = vu;
        pb.A[3] = ht; pb.W[3] = Wk; pb.b[3] = bk; pb.C[3] = kt;
        pb.A[4] = ht; pb.W[4] = Wv; pb.b[4] = bv; pb.C[4] = vt;
        dim3 grid(H_ / 128, BMrows / 128, 5);
        gemm_proj_batch<<<grid, thr>>>(pb, H_, H_);
    }

    // 2) scores[b] = scale * q[b] @ kt[b]^T   (batched NT)
    {
        dim3 grid(M_ / 128, M_ / 128, B_);
        gemm_tc<true, EPI_SCALE><<<grid, thr>>>(q, kt, nullptr, nullptr, sc,
            M_, H_, (long)M_ * H_, (long)M_ * H_, (long)M_ * M_, scale,
            nullptr, nullptr, nullptr);
    }

    // 3+4) fused: diagonal = scale*dot(q,ku), then row softmax (+ p_diag)
    softmax_kernel<<<BMrows, thr>>>(sc, q, ku, pd, scale);

    // 5) ctx[b] = probs[b] @ vt[b] + p_diag*(vu-vt)   (batched NN, fused fix)
    {
        dim3 grid(H_ / 128, M_ / 128, B_);
        gemm_tc<false, EPI_PDIAG><<<grid, thr>>>(sc, vt, nullptr, nullptr, ctx,
            H_, M_, (long)M_ * M_, (long)M_ * H_, (long)M_ * H_, 0.f,
            pd, vu, vt);
    }

    // 6) attn_out = LN1(ctx @ Wo + bo)
    {
        dim3 grid(H_ / 128, BMrows / 128, 1);
        gemm_tc<false, EPI_BIAS><<<grid, thr>>>(ctx, Wo, bo, nullptr, tmp, H_, H_, 0, 0, 0, 0.f,
            nullptr, nullptr, nullptr);
    }
    layernorm_kernel<<<BMrows, thr>>>(tmp, ln1g, ln1b, ao);

    // 7) inter = gelu_exact(attn_out @ W1 + b1)
    {
        dim3 grid(I_ / 128, BMrows / 128, 1);
        gemm_tc<false, EPI_BIAS_GELU><<<grid, thr>>>(ao, W1, b1, nullptr, inter, I_, H_, 0, 0, 0, 0.f,
            nullptr, nullptr, nullptr);
    }

    // 8) tmp = inter @ W2 + b2 + attn_out ; out = LN2(tmp)
    {
        dim3 grid(H_ / 128, BMrows / 128, 1);
        gemm_tc<false, EPI_BIAS_RES><<<grid, thr>>>(inter, W2, b2, ao, tmp, H_, I_, 0, 0, 0, 0.f,
            nullptr, nullptr, nullptr);
    }
    layernorm_kernel<<<BMrows, thr>>>(tmp, ln2g, ln2b, out);
}